// round 12
// baseline (speedup 1.0000x reference)
#include <cuda_runtime.h>
#include <cuda_fp16.h>
#include <cstdint>

#define BB 256
#define TT 2000
#define II 23
#define HH 128
#define MB 8                    // batches per CTA
#define NREC_CTAS (BB / MB)     // 32
#define NSL 10                  // k-slices of 16 (128 h + 32 x-pad)
#define HSTRIDE 168             // padded fp16 row stride (336B; conflict-free)

__device__ __forceinline__ uint32_t pack_h2(float lo, float hi) {
    uint32_t d;
    asm("cvt.rn.f16x2.f32 %0, %1, %2;" : "=r"(d) : "f"(hi), "f"(lo));
    return d;
}
__device__ __forceinline__ uint32_t tanh_h2(uint32_t v) {
    uint32_t d;
    asm("tanh.approx.f16x2 %0, %1;" : "=r"(d) : "r"(v));
    return d;
}
__device__ __forceinline__ uint32_t hfma2_(uint32_t a, uint32_t b, uint32_t c) {
    uint32_t d;
    asm("fma.rn.f16x2 %0, %1, %2, %3;" : "=r"(d) : "r"(a), "r"(b), "r"(c));
    return d;
}
__device__ __forceinline__ void ldsm_x2(uint32_t& r0, uint32_t& r1, uint32_t addr) {
    asm volatile("ldmatrix.sync.aligned.m8n8.x2.shared.b16 {%0,%1}, [%2];"
                 : "=r"(r0), "=r"(r1) : "r"(addr));
}
__device__ __forceinline__ void mma_f16(float& d0, float& d1, float& d2, float& d3,
                                        uint32_t a0, uint32_t a1, uint32_t a2, uint32_t a3,
                                        uint32_t b0, uint32_t b1,
                                        float c0, float c1, float c2, float c3) {
    asm volatile(
        "mma.sync.aligned.m16n8k16.row.col.f32.f16.f16.f32 "
        "{%0,%1,%2,%3},{%4,%5,%6,%7},{%8,%9},{%10,%11,%12,%13};"
        : "=f"(d0), "=f"(d1), "=f"(d2), "=f"(d3)
        : "r"(a0), "r"(a1), "r"(a2), "r"(a3), "r"(b0), "r"(b1),
          "f"(c0), "f"(c1), "f"(c2), "f"(c3));
}
__device__ __forceinline__ void cp_async4(uint32_t dst, const float* src) {
    asm volatile("cp.async.ca.shared.global [%0], [%1], 4;"
                 :: "r"(dst), "l"(src) : "memory");
}
__device__ __forceinline__ void cp_commit() {
    asm volatile("cp.async.commit_group;" ::: "memory");
}
__device__ __forceinline__ void cp_wait1() {
    asm volatile("cp.async.wait_group 1;" ::: "memory");
}

// ============================================================
// Fused GRU: grid 32, block 256 (8 warps), 8 batches/CTA.
// gates = [W_hh | W_ih | bias-col] . [h ; x(t) ; 1].
// r,z weight rows pre-scaled by 0.5 (sigmoid via tanh).
// x staged via cp.async double-buffer (no LDG in the chain).
// f16x2 epilogue (tanh.approx.f16x2), h-update in f32.
// ============================================================
__global__ __launch_bounds__(256, 1) void gru_fused(
    const float* __restrict__ x,     // [B, T, I]
    const float* __restrict__ Wih,   // [3H, I]
    const float* __restrict__ Whh,   // [3H, H]
    const float* __restrict__ bih,   // [3H]
    const float* __restrict__ bhh,   // [3H]
    float* __restrict__ out)         // [B, H]
{
    const int tid  = threadIdx.x;
    const int w    = tid >> 5;
    const int lane = tid & 31;
    const int g    = lane >> 2;
    const int tig  = lane & 3;
    const int bg0  = blockIdx.x * MB;

    __shared__ __align__(16) __half h_sh[2][MB][HSTRIDE];
    __shared__ __align__(16) float  xstage[2][MB][24];

    // ---- B fragments: h slices 0..7, x slices 8..9 (+bias col @ k=151) ----
    // gates r,z scaled by 0.5; gate n unscaled (bhh_n kept in regs).
    uint32_t Bf[2][3][NSL][2];
#pragma unroll
    for (int tr = 0; tr < 2; tr++) {
        const int cg = 2 * w + tr;
#pragma unroll
        for (int gate = 0; gate < 3; gate++) {
            const int orow = gate * HH + cg * 8 + g;
            const float scale = (gate < 2) ? 0.5f : 1.0f;
            const float bfold = (gate < 2) ? 0.5f * (bih[orow] + bhh[orow])
                                           : bih[orow];
            const float* WrH = Whh + (size_t)orow * HH;
#pragma unroll
            for (int ks = 0; ks < 8; ks++) {
                int c = ks * 16 + 2 * tig;
                float2 v0 = *reinterpret_cast<const float2*>(WrH + c);
                float2 v1 = *reinterpret_cast<const float2*>(WrH + c + 8);
                Bf[tr][gate][ks][0] = pack_h2(v0.x * scale, v0.y * scale);
                Bf[tr][gate][ks][1] = pack_h2(v1.x * scale, v1.y * scale);
            }
            const float* WrI = Wih + (size_t)orow * II;
#pragma unroll
            for (int s = 0; s < 2; s++) {
                int c = s * 16 + 2 * tig;
                float e0 = (c < II) ? WrI[c] * scale : 0.f;
                float e1 = (c + 1 == II) ? bfold
                         : ((c + 1 < II) ? WrI[c + 1] * scale : 0.f);
                float e2 = (c + 8 < II) ? WrI[c + 8] * scale : 0.f;
                float e3 = (c + 9 < II) ? WrI[c + 9] * scale : 0.f;
                Bf[tr][gate][8 + s][0] = pack_h2(e0, e1);
                Bf[tr][gate][8 + s][1] = pack_h2(e2, e3);
            }
        }
    }

    // b_hh for candidate gate (cannot be folded: multiplied by r)
    float bh_n[2][2];
#pragma unroll
    for (int tr = 0; tr < 2; tr++) {
        const int col = (2 * w + tr) * 8 + 2 * tig;
        bh_n[tr][0] = bhh[2 * HH + col];
        bh_n[tr][1] = bhh[2 * HH + col + 1];
    }

    // zero both buffers (h=0, x region incl. pad = 0)
    for (int i = tid; i < 2 * MB * HSTRIDE; i += 256)
        reinterpret_cast<__half*>(h_sh)[i] = __float2half(0.0f);

    // x staging roles: threads 0..95 -> (xb batch, xj word)
    const int xb = tid / 12;
    const int xj = tid % 12;
    const bool xrole = (tid < 96);
    const float* xrow = x + (size_t)(bg0 + (xrole ? xb : 0)) * TT * II;

    __syncthreads();

    // prologue: x(0) direct -> buffer 0 ; cp.async x(1) -> stage[1]
    if (xrole) {
        float e0 = xrow[2 * xj];
        float e1 = (xj < 11) ? xrow[2 * xj + 1] : 1.0f;   // k=151 const 1.0
        *reinterpret_cast<uint32_t*>(&h_sh[0][xb][HH + 2 * xj]) = pack_h2(e0, e1);
        const float* src = xrow + II;                      // t = 1
        uint32_t d = (uint32_t)__cvta_generic_to_shared(&xstage[1][xb][2 * xj]);
        cp_async4(d, src + 2 * xj);
        if (xj < 11) cp_async4(d + 4, src + 2 * xj + 1);
        cp_commit();
    }

    float hp[2][2]   = {{0.f, 0.f}, {0.f, 0.f}};
    float hsum[2][2] = {{0.f, 0.f}, {0.f, 0.f}};

    const int arow  = lane & 7;
    const int ahalf = (lane >> 3) & 1;
    uint32_t hbase[2];
    hbase[0] = (uint32_t)__cvta_generic_to_shared(&h_sh[0][0][0]) +
               arow * (HSTRIDE * 2) + ahalf * 16;
    hbase[1] = (uint32_t)__cvta_generic_to_shared(&h_sh[1][0][0]) +
               arow * (HSTRIDE * 2) + ahalf * 16;

    const uint32_t H05 = 0x38003800u;   // half2(0.5, 0.5)

    __syncthreads();

    int cur = 0;
    for (int t = 0; t < TT; t++) {
        // issue cp.async for x(t+2) into stage[t&1]
        if (xrole) {
            if (t + 2 < TT) {
                const float* src = xrow + (size_t)(t + 2) * II;
                uint32_t d = (uint32_t)__cvta_generic_to_shared(
                                 &xstage[t & 1][xb][2 * xj]);
                cp_async4(d, src + 2 * xj);
                if (xj < 11) cp_async4(d + 4, src + 2 * xj + 1);
            }
            cp_commit();   // uniform group count (empty group near the end)
        }

        // A fragments: 10 k-slices of [h ; x ; 1]
        uint32_t A0[NSL], A2[NSL];
#pragma unroll
        for (int ks = 0; ks < NSL; ks++)
            ldsm_x2(A0[ks], A2[ks], hbase[cur] + ks * 32);

        // ---- MMA chains ----
        float Dr[2][2], Dz[2][2], Dnh[2][2], Dnx[2][2];
#pragma unroll
        for (int tr = 0; tr < 2; tr++) {
            {
                float d0 = 0.f, d1 = 0.f, d2 = 0.f, d3 = 0.f;
#pragma unroll
                for (int ks = 0; ks < NSL; ks++)
                    mma_f16(d0, d1, d2, d3, A0[ks], 0u, A2[ks], 0u,
                            Bf[tr][0][ks][0], Bf[tr][0][ks][1], d0, d1, d2, d3);
                Dr[tr][0] = d0; Dr[tr][1] = d1;
            }
            {
                float d0 = 0.f, d1 = 0.f, d2 = 0.f, d3 = 0.f;
#pragma unroll
                for (int ks = 0; ks < NSL; ks++)
                    mma_f16(d0, d1, d2, d3, A0[ks], 0u, A2[ks], 0u,
                            Bf[tr][1][ks][0], Bf[tr][1][ks][1], d0, d1, d2, d3);
                Dz[tr][0] = d0; Dz[tr][1] = d1;
            }
            {
                float d0 = 0.f, d1 = 0.f, d2 = 0.f, d3 = 0.f;
#pragma unroll
                for (int ks = 0; ks < 8; ks++)
                    mma_f16(d0, d1, d2, d3, A0[ks], 0u, A2[ks], 0u,
                            Bf[tr][2][ks][0], Bf[tr][2][ks][1], d0, d1, d2, d3);
                Dnh[tr][0] = d0; Dnh[tr][1] = d1;
                float f0 = 0.f, f1 = 0.f, f2 = 0.f, f3 = 0.f;
#pragma unroll
                for (int ks = 8; ks < NSL; ks++)
                    mma_f16(f0, f1, f2, f3, A0[ks], 0u, A2[ks], 0u,
                            Bf[tr][2][ks][0], Bf[tr][2][ks][1], f0, f1, f2, f3);
                Dnx[tr][0] = f0; Dnx[tr][1] = f1;
            }
        }

        // consume staged x(t+1): LDS from stage, pack fp16
        uint32_t xw = 0u;
        const bool xdo = xrole && (t + 1 < TT);
        if (xdo) {
            cp_wait1();
            const float* sp = &xstage[(t + 1) & 1][xb][0];
            float e0 = sp[2 * xj];
            float e1 = (xj < 11) ? sp[2 * xj + 1] : 1.0f;
            xw = pack_h2(e0, e1);
        }

        // ---- f16x2 epilogue ----
#pragma unroll
        for (int tr = 0; tr < 2; tr++) {
            uint32_t sr = hfma2_(tanh_h2(pack_h2(Dr[tr][0], Dr[tr][1])), H05, H05);
            uint32_t sz = hfma2_(tanh_h2(pack_h2(Dz[tr][0], Dz[tr][1])), H05, H05);
            uint32_t dnh = pack_h2(Dnh[tr][0] + bh_n[tr][0],
                                   Dnh[tr][1] + bh_n[tr][1]);
            uint32_t dnx = pack_h2(Dnx[tr][0], Dnx[tr][1]);
            uint32_t n16 = tanh_h2(hfma2_(sr, dnh, dnx));

            float2 zf = __half22float2(*reinterpret_cast<__half2*>(&sz));
            float2 nf = __half22float2(*reinterpret_cast<__half2*>(&n16));
            float h0 = fmaf(zf.x, hp[tr][0] - nf.x, nf.x);
            float h1 = fmaf(zf.y, hp[tr][1] - nf.y, nf.y);
            hp[tr][0] = h0;  hp[tr][1] = h1;
            hsum[tr][0] += h0;  hsum[tr][1] += h1;

            const int col = (2 * w + tr) * 8 + 2 * tig;
            *reinterpret_cast<uint32_t*>(&h_sh[cur ^ 1][g][col]) = pack_h2(h0, h1);
        }

        if (xdo)
            *reinterpret_cast<uint32_t*>(&h_sh[cur ^ 1][xb][HH + 2 * xj]) = xw;

        __syncthreads();
        cur ^= 1;
    }

#pragma unroll
    for (int tr = 0; tr < 2; tr++) {
        const int col = (2 * w + tr) * 8 + 2 * tig;
        out[(bg0 + g) * HH + col]     = hsum[tr][0] * (1.0f / (float)TT);
        out[(bg0 + g) * HH + col + 1] = hsum[tr][1] * (1.0f / (float)TT);
    }
}

extern "C" void kernel_launch(void* const* d_in, const int* in_sizes, int n_in,
                              void* d_out, int out_size) {
    const float* x   = (const float*)d_in[0];
    const float* Wih = (const float*)d_in[1];
    const float* Whh = (const float*)d_in[2];
    const float* bih = (const float*)d_in[3];
    const float* bhh = (const float*)d_in[4];
    float* out = (float*)d_out;
    (void)in_sizes; (void)n_in; (void)out_size;

    gru_fused<<<NREC_CTAS, 256>>>(x, Wih, Whh, bih, bhh, out);
}